// round 1
// baseline (speedup 1.0000x reference)
#include <cuda_runtime.h>
#include <cuda_bf16.h>
#include <cstdint>

#define BATCH 8

// ---------------- scratch (device globals; no allocations allowed) ----------------
#define MAXACT (8u*64u*128u*128u)            // 8.39M floats, largest activation (layer1)
__device__ float g_bufA[MAXACT];
__device__ float g_bufB[MAXACT];
__device__ float g_col[75497472u];           // largest col: conv1_2 N=131072, K=576
__device__ int4   g_tabI[196416];            // per (pos,tap): 4 gather indices
__device__ float4 g_tabW[196416];            // per (pos,tap): 4 bilinear weights
__device__ float g_vec1[8*4096];
__device__ float g_vec2[8*4096];

// table base offsets per resolution (pos*9+k entries)
#define TB128 0
#define TB64  147456
#define TB32  184320
#define TB16  193536
#define TB8   195840

// ---------------- offset table construction ----------------
__global__ void build_tab(int H, int base) {
    int t = blockIdx.x * blockDim.x + threadIdx.x;
    int HW = H * H;
    if (t >= HW * 9) return;
    int k = t % 9, pos = t / 9;
    int y = pos / H, x = pos % H;

    float cc = 0.5f * (float)H - 0.5f;
    float th = atan2f((float)x - cc, (float)y - cc);
    if (th < 0.f) th += 6.28318530717958647692f;      // mod 2pi (f32)
    th = rintf(th * 10000.0f) / 10000.0f;             // round half-even like jnp.round

    int ky = k / 3, kx = k % 3;
    float offy = 0.f, offx = 0.f;
    if (k != 4) {
        int m = (k < 4) ? k : k - 1;
        float ang = th + (float)(3.14159265358979323846 * 0.25 * (double)m);
        offy = cosf(ang) + (float)(1 - ky);
        offx = sinf(ang) + (float)(1 - kx);
    }
    float py = (float)(y - 1 + ky) + offy;
    float px = (float)(x - 1 + kx) + offx;
    float y0 = floorf(py), x0 = floorf(px);
    float fy = py - y0, fx = px - x0;
    float Hm = (float)(H - 1);

    float ys[2] = {y0, y0 + 1.f};
    float xs[2] = {x0, x0 + 1.f};
    float wy[2] = {1.f - fy, fy};
    float wx[2] = {1.f - fx, fx};

    int   ids[4];
    float ws[4];
    int q = 0;
    #pragma unroll
    for (int iy = 0; iy < 2; iy++) {
        #pragma unroll
        for (int ix = 0; ix < 2; ix++) {
            float yf = ys[iy], xf = xs[ix];
            bool v = (yf >= 0.f) && (yf <= Hm) && (xf >= 0.f) && (xf <= Hm);
            int yi = (int)fminf(fmaxf(yf, 0.f), Hm);
            int xi = (int)fminf(fmaxf(xf, 0.f), Hm);
            ids[q] = yi * H + xi;
            ws[q]  = v ? (wy[iy] * wx[ix]) : 0.f;
            q++;
        }
    }
    g_tabI[base + t] = make_int4(ids[0], ids[1], ids[2], ids[3]);
    g_tabW[base + t] = make_float4(ws[0], ws[1], ws[2], ws[3]);
}

// ---------------- deformable im2col: col[(c*9+k)*N + n] ----------------
__global__ void im2col_deform(const float* __restrict__ x, float* __restrict__ col,
                              int Cin, int HW, int N, int tabBase) {
    int n = blockIdx.x * blockDim.x + threadIdx.x;
    int k = blockIdx.y;
    if (n >= N) return;
    int pos = n % HW;
    int b   = n / HW;
    int4   id = g_tabI[tabBase + pos * 9 + k];
    float4 w  = g_tabW[tabBase + pos * 9 + k];
    const float* xb = x + (size_t)b * Cin * HW;
    float* cp = col + (size_t)k * N + n;
    size_t cstride = (size_t)9 * N;
    for (int c = 0; c < Cin; c++) {
        const float* xc = xb + (size_t)c * HW;
        float v = xc[id.x] * w.x + xc[id.y] * w.y + xc[id.z] * w.z + xc[id.w] * w.w;
        cp[(size_t)c * cstride] = v;
    }
}

// ---------------- SGEMM with fused ReLU: out[b][o][pos] = relu(sum_K col[K][n]*W[o][K]) ----------------
__global__ __launch_bounds__(256)
void gemm_relu(const float* __restrict__ A,   // col, K x N (row stride N)
               const float* __restrict__ Wt,  // O x K row-major
               float* __restrict__ out, int N, int K, int Cout, int HW, int doRelu) {
    __shared__ float As[16][68];
    __shared__ float Bs[16][68];
    int tid = threadIdx.x;
    int bn = blockIdx.x * 64, bo = blockIdx.y * 64;
    int tx = tid & 15, ty = tid >> 4;

    float acc[4][4];
    #pragma unroll
    for (int i = 0; i < 4; i++)
        #pragma unroll
        for (int j = 0; j < 4; j++) acc[i][j] = 0.f;

    int la_k = tid >> 4;           // 0..15
    int la_n = (tid & 15) * 4;     // 0..60
    int lb_o = tid >> 2;           // 0..63
    int lb_k = (tid & 3) * 4;      // 0..12

    for (int k0 = 0; k0 < K; k0 += 16) {
        int ka = k0 + la_k;
        float4 av = make_float4(0.f, 0.f, 0.f, 0.f);
        if (ka < K) av = *(const float4*)&A[(size_t)ka * N + bn + la_n];
        *(float4*)&As[la_k][la_n] = av;

        const float* wr = Wt + (size_t)(bo + lb_o) * K;
        #pragma unroll
        for (int j = 0; j < 4; j++) {
            int kb = k0 + lb_k + j;
            Bs[lb_k + j][lb_o] = (kb < K) ? wr[kb] : 0.f;
        }
        __syncthreads();

        #pragma unroll
        for (int kk = 0; kk < 16; kk++) {
            float4 a4 = *(const float4*)&As[kk][ty * 4];
            float4 b4 = *(const float4*)&Bs[kk][tx * 4];
            float ar[4] = {a4.x, a4.y, a4.z, a4.w};
            float br[4] = {b4.x, b4.y, b4.z, b4.w};
            #pragma unroll
            for (int i = 0; i < 4; i++)
                #pragma unroll
                for (int j = 0; j < 4; j++)
                    acc[i][j] = fmaf(ar[i], br[j], acc[i][j]);
        }
        __syncthreads();
    }

    int b = bn / HW;         // tiles never cross batch images (HW % 64 == 0)
    int pos0 = bn % HW;
    #pragma unroll
    for (int i = 0; i < 4; i++) {
        int pos = pos0 + ty * 4 + i;
        #pragma unroll
        for (int j = 0; j < 4; j++) {
            int o = bo + tx * 4 + j;
            float v = acc[i][j];
            if (doRelu) v = fmaxf(v, 0.f);
            out[((size_t)b * Cout + o) * HW + pos] = v;
        }
    }
}

// ---------------- 2x2 maxpool ----------------
__global__ void maxpool2(const float* __restrict__ in, float* __restrict__ out, int C, int H) {
    int Ho = H >> 1;
    int total = BATCH * C * Ho * Ho;
    int t = blockIdx.x * blockDim.x + threadIdx.x;
    if (t >= total) return;
    int xo = t % Ho;
    int tmp = t / Ho;
    int yo = tmp % Ho;
    int bc = tmp / Ho;
    const float* p = in + ((size_t)bc * H + 2 * yo) * H + 2 * xo;
    out[t] = fmaxf(fmaxf(p[0], p[1]), fmaxf(p[H], p[H + 1]));
}

// ---------------- 4x4 average pool -> (B,512) ----------------
__global__ void avgpool4(const float* __restrict__ in, float* __restrict__ out) {
    int t = blockIdx.x * blockDim.x + threadIdx.x;
    if (t >= BATCH * 512) return;
    const float* p = in + (size_t)t * 16;
    float s = 0.f;
    #pragma unroll
    for (int i = 0; i < 16; i++) s += p[i];
    out[t] = s * (1.f / 16.f);
}

// ---------------- FC: warp per output neuron, all 8 batches ----------------
__global__ void fc_kernel(const float* __restrict__ v, const float* __restrict__ Wf,
                          const float* __restrict__ bias, float* __restrict__ out,
                          int In, int Out, int doRelu) {
    int warp = (blockIdx.x * blockDim.x + threadIdx.x) >> 5;
    int lane = threadIdx.x & 31;
    if (warp >= Out) return;
    const float* wrow = Wf + (size_t)warp * In;
    float acc[BATCH];
    #pragma unroll
    for (int b = 0; b < BATCH; b++) acc[b] = 0.f;
    for (int i = lane; i < In; i += 32) {
        float wv = wrow[i];
        #pragma unroll
        for (int b = 0; b < BATCH; b++)
            acc[b] = fmaf(wv, v[b * In + i], acc[b]);
    }
    #pragma unroll
    for (int b = 0; b < BATCH; b++) {
        #pragma unroll
        for (int off = 16; off; off >>= 1)
            acc[b] += __shfl_xor_sync(0xffffffffu, acc[b], off);
    }
    if (lane == 0) {
        float bi = bias[warp];
        #pragma unroll
        for (int b = 0; b < BATCH; b++) {
            float r = acc[b] + bi;
            if (doRelu) r = fmaxf(r, 0.f);
            out[b * Out + warp] = r;
        }
    }
}

// ---------------- host orchestration ----------------
static void conv_layer(const float* in, float* out, const float* wt, float* col,
                       int Cin, int Cout, int H, int tabBase) {
    int HW = H * H;
    int N = BATCH * HW;
    dim3 gi((N + 255) / 256, 9);
    im2col_deform<<<gi, 256>>>(in, col, Cin, HW, N, tabBase);
    dim3 gg(N / 64, Cout / 64);
    gemm_relu<<<gg, 256>>>(col, wt, out, N, Cin * 9, Cout, HW, 1);
}

extern "C" void kernel_launch(void* const* d_in, const int* in_sizes, int n_in,
                              void* d_out, int out_size) {
    const float* x = (const float*)d_in[0];
    const float* w11 = (const float*)d_in[1];
    const float* w12 = (const float*)d_in[2];
    const float* w21 = (const float*)d_in[3];
    const float* w22 = (const float*)d_in[4];
    const float* w31 = (const float*)d_in[5];
    const float* w32 = (const float*)d_in[6];
    const float* w33 = (const float*)d_in[7];
    const float* w41 = (const float*)d_in[8];
    const float* w42 = (const float*)d_in[9];
    const float* w43 = (const float*)d_in[10];
    const float* w51 = (const float*)d_in[11];
    const float* w52 = (const float*)d_in[12];
    const float* w53 = (const float*)d_in[13];
    const float* fc1w = (const float*)d_in[14];
    const float* fc1b = (const float*)d_in[15];
    const float* fc2w = (const float*)d_in[16];
    const float* fc2b = (const float*)d_in[17];
    const float* fc3w = (const float*)d_in[18];
    const float* fc3b = (const float*)d_in[19];
    float* outp = (float*)d_out;

    float *bufA, *bufB, *col, *vec1, *vec2;
    cudaGetSymbolAddress((void**)&bufA, g_bufA);
    cudaGetSymbolAddress((void**)&bufB, g_bufB);
    cudaGetSymbolAddress((void**)&col,  g_col);
    cudaGetSymbolAddress((void**)&vec1, g_vec1);
    cudaGetSymbolAddress((void**)&vec2, g_vec2);

    // offset tables (cheap, deterministic, rebuilt every call)
    build_tab<<<(128*128*9 + 255) / 256, 256>>>(128, TB128);
    build_tab<<<(64*64*9   + 255) / 256, 256>>>(64,  TB64);
    build_tab<<<(32*32*9   + 255) / 256, 256>>>(32,  TB32);
    build_tab<<<(16*16*9   + 255) / 256, 256>>>(16,  TB16);
    build_tab<<<(8*8*9     + 255) / 256, 256>>>(8,   TB8);

    // block 1 (128x128)
    conv_layer(x,    bufA, w11, col,   3,  64, 128, TB128);
    conv_layer(bufA, bufB, w12, col,  64,  64, 128, TB128);
    maxpool2<<<(BATCH*64*64*64 + 255) / 256, 256>>>(bufB, bufA, 64, 128);
    // block 2 (64x64)
    conv_layer(bufA, bufB, w21, col,  64, 128, 64, TB64);
    conv_layer(bufB, bufA, w22, col, 128, 128, 64, TB64);
    maxpool2<<<(BATCH*128*32*32 + 255) / 256, 256>>>(bufA, bufB, 128, 64);
    // block 3 (32x32)
    conv_layer(bufB, bufA, w31, col, 128, 256, 32, TB32);
    conv_layer(bufA, bufB, w32, col, 256, 256, 32, TB32);
    conv_layer(bufB, bufA, w33, col, 256, 256, 32, TB32);
    maxpool2<<<(BATCH*256*16*16 + 255) / 256, 256>>>(bufA, bufB, 256, 32);
    // block 4 (16x16)
    conv_layer(bufB, bufA, w41, col, 256, 512, 16, TB16);
    conv_layer(bufA, bufB, w42, col, 512, 512, 16, TB16);
    conv_layer(bufB, bufA, w43, col, 512, 512, 16, TB16);
    maxpool2<<<(BATCH*512*8*8 + 255) / 256, 256>>>(bufA, bufB, 512, 16);
    // block 5 (8x8)
    conv_layer(bufB, bufA, w51, col, 512, 512, 8, TB8);
    conv_layer(bufA, bufB, w52, col, 512, 512, 8, TB8);
    conv_layer(bufB, bufA, w53, col, 512, 512, 8, TB8);
    maxpool2<<<(BATCH*512*4*4 + 255) / 256, 256>>>(bufA, bufB, 512, 8);

    // head
    avgpool4<<<(BATCH*512 + 255) / 256, 256>>>(bufB, vec1);
    fc_kernel<<<(4096*32 + 255) / 256, 256>>>(vec1, fc1w, fc1b, vec2, 512, 4096, 1);
    fc_kernel<<<(4096*32 + 255) / 256, 256>>>(vec2, fc2w, fc2b, vec1, 4096, 4096, 1);
    fc_kernel<<<(30*32   + 255) / 256, 256>>>(vec1, fc3w, fc3b, outp, 4096, 30, 0);
}